// round 2
// baseline (speedup 1.0000x reference)
#include <cuda_runtime.h>

#define TT 50
#define NN 12
#define MM 4
#define NSC2 16
#define NBATCH 8192
#define BK 64
#define NSYM 78   // 12*13/2 symmetric-packed

// Gains scratch: [step s][entry e (0..51)][batch b]  (52 = 48 K + 4 kff)
__device__ float g_gains[TT * 52 * NBATCH];

__device__ __forceinline__ int symidx(int i, int j) {
    int a = i < j ? i : j;
    int c = i < j ? j : i;
    return a * NN - (a * (a + 1)) / 2 + c;
}

__global__ void __launch_bounds__(BK) bwd_kernel(
    const float* __restrict__ Qg, const float* __restrict__ pg,
    const float* __restrict__ Ag, const float* __restrict__ Bg)
{
    __shared__ float sm[192 + 2 * NSYM * BK];
    const int tid = threadIdx.x;
    const int b = blockIdx.x * BK + tid;

    for (int e = tid; e < 192; e += BK) sm[e] = (e < 144) ? Ag[e] : Bg[e - 144];
    __syncthreads();
    const float* sA = sm;          // A[i*12+j]
    const float* sB = sm + 144;    // B[i*4+m]
    float* Vbuf0 = sm + 192 + tid;             // element e at Vbuf0[e*BK]
    float* Vbuf1 = Vbuf0 + NSYM * BK;

    // Per-batch cost weights
    float Qx[NN], Qu[MM], px[NN], pu[MM];
    {
        const float4* q4 = reinterpret_cast<const float4*>(Qg + b * NSC2);
        float4 a0 = q4[0], a1 = q4[1], a2 = q4[2], a3 = q4[3];
        Qx[0]=a0.x; Qx[1]=a0.y; Qx[2]=a0.z; Qx[3]=a0.w;
        Qx[4]=a1.x; Qx[5]=a1.y; Qx[6]=a1.z; Qx[7]=a1.w;
        Qx[8]=a2.x; Qx[9]=a2.y; Qx[10]=a2.z; Qx[11]=a2.w;
        Qu[0]=a3.x; Qu[1]=a3.y; Qu[2]=a3.z; Qu[3]=a3.w;
        const float4* p4 = reinterpret_cast<const float4*>(pg + b * NSC2);
        float4 b0 = p4[0], b1 = p4[1], b2 = p4[2], b3 = p4[3];
        px[0]=b0.x; px[1]=b0.y; px[2]=b0.z; px[3]=b0.w;
        px[4]=b1.x; px[5]=b1.y; px[6]=b1.z; px[7]=b1.w;
        px[8]=b2.x; px[9]=b2.y; px[10]=b2.z; px[11]=b2.w;
        pu[0]=b3.x; pu[1]=b3.y; pu[2]=b3.z; pu[3]=b3.w;
    }

    // V = 0, v = 0
    #pragma unroll
    for (int e = 0; e < NSYM; e++) Vbuf0[e * BK] = 0.0f;
    float v[NN];
    #pragma unroll
    for (int i = 0; i < NN; i++) v[i] = 0.0f;

    #pragma unroll 1
    for (int s = 0; s < TT; s++) {
        float* Vr = (s & 1) ? Vbuf1 : Vbuf0;
        float* Vw = (s & 1) ? Vbuf0 : Vbuf1;

        // ---- VB = V * B  (12x4) ----
        float VB[NN][MM];
        #pragma unroll
        for (int i = 0; i < NN; i++)
            #pragma unroll
            for (int m = 0; m < MM; m++) VB[i][m] = 0.0f;
        #pragma unroll
        for (int j = 0; j < NN; j++) {
            float bj0 = sB[j*MM+0], bj1 = sB[j*MM+1], bj2 = sB[j*MM+2], bj3 = sB[j*MM+3];
            #pragma unroll
            for (int i = 0; i < NN; i++) {
                float vij = Vr[symidx(i, j) * BK];
                VB[i][0] += vij * bj0;
                VB[i][1] += vij * bj1;
                VB[i][2] += vij * bj2;
                VB[i][3] += vij * bj3;
            }
        }

        // ---- Quu = diag(Qu) + B^T VB ; qu = pu + B^T v ----
        float Quu[MM][MM];
        float qu[MM];
        #pragma unroll
        for (int m = 0; m < MM; m++) {
            qu[m] = pu[m];
            #pragma unroll
            for (int n2 = m; n2 < MM; n2++) Quu[m][n2] = (m == n2) ? Qu[m] : 0.0f;
        }
        #pragma unroll
        for (int i = 0; i < NN; i++) {
            float bi0 = sB[i*MM+0], bi1 = sB[i*MM+1], bi2 = sB[i*MM+2], bi3 = sB[i*MM+3];
            qu[0] += bi0 * v[i]; qu[1] += bi1 * v[i];
            qu[2] += bi2 * v[i]; qu[3] += bi3 * v[i];
            Quu[0][0] += bi0 * VB[i][0]; Quu[0][1] += bi0 * VB[i][1];
            Quu[0][2] += bi0 * VB[i][2]; Quu[0][3] += bi0 * VB[i][3];
            Quu[1][1] += bi1 * VB[i][1]; Quu[1][2] += bi1 * VB[i][2];
            Quu[1][3] += bi1 * VB[i][3];
            Quu[2][2] += bi2 * VB[i][2]; Quu[2][3] += bi2 * VB[i][3];
            Quu[3][3] += bi3 * VB[i][3];
        }
        Quu[1][0] = Quu[0][1]; Quu[2][0] = Quu[0][2]; Quu[3][0] = Quu[0][3];
        Quu[2][1] = Quu[1][2]; Quu[3][1] = Quu[1][3]; Quu[3][2] = Quu[2][3];

        // ---- M = A^T VB  (Qxu, 12x4) ----
        float Mx[NN][MM];
        #pragma unroll
        for (int n = 0; n < NN; n++)
            #pragma unroll
            for (int m = 0; m < MM; m++) Mx[n][m] = 0.0f;
        #pragma unroll
        for (int i = 0; i < NN; i++) {
            #pragma unroll
            for (int n = 0; n < NN; n++) {
                float ain = sA[i*NN+n];
                Mx[n][0] += ain * VB[i][0];
                Mx[n][1] += ain * VB[i][1];
                Mx[n][2] += ain * VB[i][2];
                Mx[n][3] += ain * VB[i][3];
            }
        }

        // ---- Cholesky of Quu (SPD) ----
        float l00 = sqrtf(Quu[0][0]);           float i00 = 1.0f / l00;
        float L10 = Quu[1][0] * i00;
        float L20 = Quu[2][0] * i00;
        float L30 = Quu[3][0] * i00;
        float l11 = sqrtf(Quu[1][1] - L10*L10); float i11 = 1.0f / l11;
        float L21 = (Quu[2][1] - L20*L10) * i11;
        float L31 = (Quu[3][1] - L30*L10) * i11;
        float l22 = sqrtf(Quu[2][2] - L20*L20 - L21*L21); float i22 = 1.0f / l22;
        float L32 = (Quu[3][2] - L30*L20 - L31*L21) * i22;
        float l33 = sqrtf(Quu[3][3] - L30*L30 - L31*L31 - L32*L32); float i33 = 1.0f / l33;

        // ---- K = -Quu^{-1} Qux  (Qux[:,n] = Mx[n][:]) ; kff = -Quu^{-1} qu ----
        float K[MM][NN], kff[MM];
        #pragma unroll
        for (int n = 0; n < NN; n++) {
            float y0 = Mx[n][0] * i00;
            float y1 = (Mx[n][1] - L10*y0) * i11;
            float y2 = (Mx[n][2] - L20*y0 - L21*y1) * i22;
            float y3 = (Mx[n][3] - L30*y0 - L31*y1 - L32*y2) * i33;
            float z3 = y3 * i33;
            float z2 = (y2 - L32*z3) * i22;
            float z1 = (y1 - L21*z2 - L31*z3) * i11;
            float z0 = (y0 - L10*z1 - L20*z2 - L30*z3) * i00;
            K[0][n] = -z0; K[1][n] = -z1; K[2][n] = -z2; K[3][n] = -z3;
        }
        {
            float y0 = qu[0] * i00;
            float y1 = (qu[1] - L10*y0) * i11;
            float y2 = (qu[2] - L20*y0 - L21*y1) * i22;
            float y3 = (qu[3] - L30*y0 - L31*y1 - L32*y2) * i33;
            float z3 = y3 * i33;
            float z2 = (y2 - L32*z3) * i22;
            float z1 = (y1 - L21*z2 - L31*z3) * i11;
            float z0 = (y0 - L10*z1 - L20*z2 - L30*z3) * i00;
            kff[0] = -z0; kff[1] = -z1; kff[2] = -z2; kff[3] = -z3;
        }

        // ---- store gains, coalesced across b ----
        {
            int base = (s * 52) * NBATCH + b;
            #pragma unroll
            for (int m = 0; m < MM; m++)
                #pragma unroll
                for (int n = 0; n < NN; n++)
                    g_gains[base + (m*NN + n) * NBATCH] = K[m][n];
            #pragma unroll
            for (int m = 0; m < MM; m++)
                g_gains[base + (48 + m) * NBATCH] = kff[m];
        }

        // ---- Vn = diag(Qx) + A^T V A + M K + (M K)^T + K^T Quu K  (upper tri) ----
        #pragma unroll
        for (int blk = 0; blk < 3; blk++) {
            const int c0 = blk * 4;
            // P[:,cc] = V * A[:, c0+cc]
            float P[NN][4];
            #pragma unroll
            for (int i = 0; i < NN; i++)
                #pragma unroll
                for (int cc = 0; cc < 4; cc++) P[i][cc] = 0.0f;
            #pragma unroll
            for (int j = 0; j < NN; j++) {
                float a0 = sA[j*NN + c0+0], a1 = sA[j*NN + c0+1];
                float a2 = sA[j*NN + c0+2], a3 = sA[j*NN + c0+3];
                #pragma unroll
                for (int i = 0; i < NN; i++) {
                    float vij = Vr[symidx(i, j) * BK];
                    P[i][0] += vij * a0;
                    P[i][1] += vij * a1;
                    P[i][2] += vij * a2;
                    P[i][3] += vij * a3;
                }
            }
            // tq[m][cc] = (Quu K)[m][c0+cc]
            float tq[MM][4];
            #pragma unroll
            for (int m = 0; m < MM; m++)
                #pragma unroll
                for (int cc = 0; cc < 4; cc++) {
                    float acc = 0.0f;
                    #pragma unroll
                    for (int pI = 0; pI < MM; pI++) acc += Quu[m][pI] * K[pI][c0+cc];
                    tq[m][cc] = acc;
                }
            #pragma unroll
            for (int r = 0; r < NN; r++) {
                if (r > c0 + 3) continue;   // folds at compile time
                float ar[NN];
                #pragma unroll
                for (int i = 0; i < NN; i++) ar[i] = sA[i*NN + r];
                #pragma unroll
                for (int cc = 0; cc < 4; cc++) {
                    const int c = c0 + cc;
                    if (r <= c) {
                        float val = (r == c) ? Qx[r] : 0.0f;
                        #pragma unroll
                        for (int i = 0; i < NN; i++) val += ar[i] * P[i][cc];
                        #pragma unroll
                        for (int m = 0; m < MM; m++)
                            val += Mx[r][m] * K[m][c] + Mx[c][m] * K[m][r];
                        #pragma unroll
                        for (int m = 0; m < MM; m++) val += K[m][r] * tq[m][cc];
                        Vw[symidx(r, c) * BK] = val;
                    }
                }
            }
        }

        // ---- vn = px + A^T v + M kff + K^T (qu + Quu kff) ----
        float tk[MM];
        #pragma unroll
        for (int m = 0; m < MM; m++) {
            float acc = 0.0f;
            #pragma unroll
            for (int pI = 0; pI < MM; pI++) acc += Quu[m][pI] * kff[pI];
            tk[m] = acc + qu[m];
        }
        float vn[NN];
        #pragma unroll
        for (int n = 0; n < NN; n++) vn[n] = px[n];
        #pragma unroll
        for (int i = 0; i < NN; i++) {
            float vi = v[i];
            #pragma unroll
            for (int n = 0; n < NN; n++) vn[n] += sA[i*NN + n] * vi;
        }
        #pragma unroll
        for (int n = 0; n < NN; n++) {
            float acc = vn[n];
            #pragma unroll
            for (int m = 0; m < MM; m++) acc += Mx[n][m] * kff[m] + K[m][n] * tk[m];
            v[n] = acc;
        }
    }
}

__global__ void __launch_bounds__(BK) fwd_kernel(
    const float* __restrict__ x_init, const float* __restrict__ Ag,
    const float* __restrict__ Bg, float* __restrict__ out)
{
    __shared__ float sm[192];
    const int tid = threadIdx.x;
    const int b = blockIdx.x * BK + tid;
    for (int e = tid; e < 192; e += BK) sm[e] = (e < 144) ? Ag[e] : Bg[e - 144];
    __syncthreads();
    const float* sA = sm;
    const float* sB = sm + 144;

    float x[NN];
    #pragma unroll
    for (int i = 0; i < NN; i++) x[i] = x_init[b * NN + i];

    #pragma unroll 1
    for (int t = 0; t < TT; t++) {
        const int s = TT - 1 - t;           // gains stored in backward order
        const int base = (s * 52) * NBATCH + b;
        float K[MM][NN], kff[MM];
        #pragma unroll
        for (int m = 0; m < MM; m++)
            #pragma unroll
            for (int n = 0; n < NN; n++)
                K[m][n] = g_gains[base + (m*NN + n) * NBATCH];
        #pragma unroll
        for (int m = 0; m < MM; m++) kff[m] = g_gains[base + (48 + m) * NBATCH];

        float u[MM];
        #pragma unroll
        for (int m = 0; m < MM; m++) {
            float acc = kff[m];
            #pragma unroll
            for (int n = 0; n < NN; n++) acc += K[m][n] * x[n];
            u[m] = acc;
        }
        float xn[NN];
        #pragma unroll
        for (int i = 0; i < NN; i++) {
            float acc = 0.0f;
            #pragma unroll
            for (int j = 0; j < NN; j++) acc += sA[i*NN + j] * x[j];
            #pragma unroll
            for (int m = 0; m < MM; m++) acc += sB[i*MM + m] * u[m];
            xn[i] = acc;
        }
        #pragma unroll
        for (int i = 0; i < NN; i++) x[i] = xn[i];

        float4 uo;
        uo.x = u[0]; uo.y = u[1]; uo.z = u[2]; uo.w = u[3];
        *reinterpret_cast<float4*>(out + ((size_t)t * NBATCH + b) * MM) = uo;
    }
}

extern "C" void kernel_launch(void* const* d_in, const int* in_sizes, int n_in,
                              void* d_out, int out_size) {
    const float* x_init = (const float*)d_in[0];
    const float* Q      = (const float*)d_in[1];
    const float* p      = (const float*)d_in[2];
    const float* A      = (const float*)d_in[3];
    const float* B      = (const float*)d_in[4];
    float* out = (float*)d_out;

    bwd_kernel<<<NBATCH / BK, BK>>>(Q, p, A, B);
    fwd_kernel<<<NBATCH / BK, BK>>>(x_init, A, B, out);
}